// round 1
// baseline (speedup 1.0000x reference)
#include <cuda_runtime.h>
#include <cuda_bf16.h>

#define SEQ 4096
#define EMB 1024

// Static device scratch (allocation-free per harness rules)
__device__ float g_Q[(size_t)SEQ * EMB];
__device__ float g_K[(size_t)SEQ * EMB];
__device__ float g_V[(size_t)SEQ * EMB];
__device__ float g_S[(size_t)SEQ * SEQ];

// ---------------------------------------------------------------------------
// Tiled fp32 GEMM: C[M,N] = alpha * A[M,K] @ op(B)
//   TRANSB=false: B is [K,N] row-major (NN)
//   TRANSB=true : B is [N,K] row-major (NT, C = A @ B^T)
// BM=BN=128, BK=8, 256 threads, 8x8 per thread.
// All shapes here are multiples of 128 (M,N) and 8 (K) -> no bounds checks.
// ---------------------------------------------------------------------------
template <bool TRANSB>
__global__ void __launch_bounds__(256) sgemm_kernel(
    const float* __restrict__ A, const float* __restrict__ B,
    float* __restrict__ C, int M, int N, int K, float alpha)
{
    __shared__ float As[8][128];
    __shared__ float Bs[8][128];

    const int tid = threadIdx.x;
    const int bm  = blockIdx.y * 128;
    const int bn  = blockIdx.x * 128;
    const int tx  = (tid & 15) * 8;   // output col offset within tile
    const int ty  = (tid >> 4) * 8;   // output row offset within tile

    // Loader mapping: 256 threads, each loads one float4 of A (and of B)
    const int la_row = tid >> 1;            // 0..127
    const int la_seg = (tid & 1) * 4;       // 0 or 4 (along K)
    const int lb_row = tid >> 5;            // 0..7   (NN: K-row)
    const int lb_col = (tid & 31) * 4;      // 0..124 (NN: N-col)

    float acc[8][8];
    #pragma unroll
    for (int i = 0; i < 8; i++)
        #pragma unroll
        for (int j = 0; j < 8; j++) acc[i][j] = 0.0f;

    for (int k0 = 0; k0 < K; k0 += 8) {
        // A tile: rows bm..bm+127, cols k0..k0+7, stored K-major in smem
        {
            float4 a4 = *reinterpret_cast<const float4*>(
                &A[(size_t)(bm + la_row) * K + k0 + la_seg]);
            As[la_seg + 0][la_row] = a4.x;
            As[la_seg + 1][la_row] = a4.y;
            As[la_seg + 2][la_row] = a4.z;
            As[la_seg + 3][la_row] = a4.w;
        }
        if (TRANSB) {
            // B is [N,K]; tile rows bn..bn+127 (N), cols k0..k0+7 (K)
            float4 b4 = *reinterpret_cast<const float4*>(
                &B[(size_t)(bn + la_row) * K + k0 + la_seg]);
            Bs[la_seg + 0][la_row] = b4.x;
            Bs[la_seg + 1][la_row] = b4.y;
            Bs[la_seg + 2][la_row] = b4.z;
            Bs[la_seg + 3][la_row] = b4.w;
        } else {
            // B is [K,N]; tile rows k0..k0+7, cols bn..bn+127
            float4 b4 = *reinterpret_cast<const float4*>(
                &B[(size_t)(k0 + lb_row) * N + bn + lb_col]);
            *reinterpret_cast<float4*>(&Bs[lb_row][lb_col]) = b4;
        }
        __syncthreads();

        #pragma unroll
        for (int k = 0; k < 8; k++) {
            float a[8], b[8];
            #pragma unroll
            for (int i = 0; i < 8; i++) a[i] = As[k][ty + i];
            #pragma unroll
            for (int j = 0; j < 8; j++) b[j] = Bs[k][tx + j];
            #pragma unroll
            for (int i = 0; i < 8; i++)
                #pragma unroll
                for (int j = 0; j < 8; j++)
                    acc[i][j] = fmaf(a[i], b[j], acc[i][j]);
        }
        __syncthreads();
    }

    // Epilogue: scale + vectorized store
    #pragma unroll
    for (int i = 0; i < 8; i++) {
        float* crow = &C[(size_t)(bm + ty + i) * N + bn + tx];
        float4 v0 = make_float4(acc[i][0] * alpha, acc[i][1] * alpha,
                                acc[i][2] * alpha, acc[i][3] * alpha);
        float4 v1 = make_float4(acc[i][4] * alpha, acc[i][5] * alpha,
                                acc[i][6] * alpha, acc[i][7] * alpha);
        reinterpret_cast<float4*>(crow)[0] = v0;
        reinterpret_cast<float4*>(crow)[1] = v1;
    }
}

// ---------------------------------------------------------------------------
// Row softmax over S [SEQ, SEQ], in place. One block per row, 256 threads,
// 16 elements per thread held in registers.
// ---------------------------------------------------------------------------
__global__ void __launch_bounds__(256) softmax_kernel(float* __restrict__ S)
{
    __shared__ float red[256];
    const size_t row = blockIdx.x;
    float* p = S + row * (size_t)SEQ;
    const int t = threadIdx.x;

    float v[16];
    float m = -3.402823e38f;
    #pragma unroll
    for (int i = 0; i < 16; i++) {
        v[i] = p[t + i * 256];
        m = fmaxf(m, v[i]);
    }
    red[t] = m;
    __syncthreads();
    #pragma unroll
    for (int s = 128; s > 0; s >>= 1) {
        if (t < s) red[t] = fmaxf(red[t], red[t + s]);
        __syncthreads();
    }
    m = red[0];
    __syncthreads();

    float sum = 0.0f;
    #pragma unroll
    for (int i = 0; i < 16; i++) {
        v[i] = __expf(v[i] - m);
        sum += v[i];
    }
    red[t] = sum;
    __syncthreads();
    #pragma unroll
    for (int s = 128; s > 0; s >>= 1) {
        if (t < s) red[t] += red[t + s];
        __syncthreads();
    }
    const float inv = 1.0f / red[0];

    #pragma unroll
    for (int i = 0; i < 16; i++)
        p[t + i * 256] = v[i] * inv;
}

// ---------------------------------------------------------------------------
extern "C" void kernel_launch(void* const* d_in, const int* in_sizes, int n_in,
                              void* d_out, int out_size)
{
    const float* x  = (const float*)d_in[0];
    const float* Wq = (const float*)d_in[1];
    const float* Wk = (const float*)d_in[2];
    const float* Wv = (const float*)d_in[3];
    float* out = (float*)d_out;

    float *Q, *K, *V, *S;
    cudaGetSymbolAddress((void**)&Q, g_Q);
    cudaGetSymbolAddress((void**)&K, g_K);
    cudaGetSymbolAddress((void**)&V, g_V);
    cudaGetSymbolAddress((void**)&S, g_S);

    const dim3 blk(256);
    const dim3 gProj(EMB / 128, SEQ / 128);   // 8 x 32
    const dim3 gScore(SEQ / 128, SEQ / 128);  // 32 x 32

    // Projections: Q = x @ Wq, K = x @ Wk, V = x @ Wv
    sgemm_kernel<false><<<gProj, blk>>>(x, Wq, Q, SEQ, EMB, EMB, 1.0f);
    sgemm_kernel<false><<<gProj, blk>>>(x, Wk, K, SEQ, EMB, EMB, 1.0f);
    sgemm_kernel<false><<<gProj, blk>>>(x, Wv, V, SEQ, EMB, EMB, 1.0f);

    // Scores: S = (Q @ K^T) / sqrt(1024)
    sgemm_kernel<true><<<gScore, blk>>>(Q, K, S, SEQ, SEQ, EMB, 0.03125f);

    // Softmax rows in place
    softmax_kernel<<<SEQ, blk>>>(S);

    // Output: out = P @ V
    sgemm_kernel<false><<<gProj, blk>>>(S, V, out, SEQ, EMB, SEQ, 1.0f);
}

// round 2
// speedup vs baseline: 1.4317x; 1.4317x over previous
#include <cuda_runtime.h>
#include <cstdint>

#define SEQ 4096
#define EMB 1024

// Static device scratch (allocation-free per harness rules)
__device__ float g_Q[(size_t)SEQ * EMB];
__device__ float g_K[(size_t)SEQ * EMB];
__device__ float g_V[(size_t)SEQ * EMB];
__device__ float g_S[(size_t)SEQ * SEQ];

__device__ __forceinline__ uint32_t f2tf(float f) {
    uint32_t u;
    asm("cvt.rna.tf32.f32 %0, %1;" : "=r"(u) : "f"(f));
    return u;
}

__device__ __forceinline__ void mma_tf32(
    float& c0, float& c1, float& c2, float& c3,
    uint32_t a0, uint32_t a1, uint32_t a2, uint32_t a3,
    uint32_t b0, uint32_t b1)
{
    asm volatile(
        "mma.sync.aligned.m16n8k8.row.col.f32.tf32.tf32.f32 "
        "{%0,%1,%2,%3}, {%4,%5,%6,%7}, {%8,%9}, {%0,%1,%2,%3};"
        : "+f"(c0), "+f"(c1), "+f"(c2), "+f"(c3)
        : "r"(a0), "r"(a1), "r"(a2), "r"(a3), "r"(b0), "r"(b1));
}

// ---------------------------------------------------------------------------
// TF32 tensor-core GEMM: C[M,N] = alpha * A[M,K] @ op(B)
//   TRANSB=false: B is [K,N] row-major  (NN)
//   TRANSB=true : B is [N,K] row-major  (NT, C = A @ B^T)
// BM=BN=128, BK=16, 256 threads (8 warps, 2x4), 64x32 per warp,
// 4x4 grid of m16n8k8 mma per warp per k8.
// A smem: [128][20] (row-major, pad 20 -> conflict-free frag loads)
// B smem: TRANSB -> [128][20] like A; NN -> [16][132] k-major.
// Shapes: M,N multiples of 128, K multiple of 16. No bounds checks.
// ---------------------------------------------------------------------------
template <bool TRANSB>
__global__ void __launch_bounds__(256, 1) mm_tf32(
    const float* __restrict__ A, const float* __restrict__ B,
    float* __restrict__ C, int M, int N, int K, float alpha)
{
    constexpr int APAD = 20;                       // words per A/B(NT) smem row
    constexpr int BSZ  = TRANSB ? 128 * 20 : 16 * 132;

    __shared__ uint32_t As[2][128 * APAD];
    __shared__ uint32_t Bs[2][BSZ];

    const int tid  = threadIdx.x;
    const int warp = tid >> 5;
    const int lane = tid & 31;
    const int g    = lane >> 2;   // group (row within frag)
    const int t    = lane & 3;    // thread-in-group
    const int wm   = warp & 1;    // warp row  (2 x 64)
    const int wn   = warp >> 1;   // warp col  (4 x 32)
    const int bm   = blockIdx.y * 128;
    const int bn   = blockIdx.x * 128;

    float acc[4][4][4];
    #pragma unroll
    for (int mi = 0; mi < 4; mi++)
        #pragma unroll
        for (int ni = 0; ni < 4; ni++)
            #pragma unroll
            for (int r = 0; r < 4; r++) acc[mi][ni][r] = 0.0f;

    float4 ra[2], rb[2];

    // ---- global fetch into registers for k-tile starting at k0 ----
    auto fetch = [&](int k0) {
        #pragma unroll
        for (int i = 0; i < 2; i++) {
            int idx = tid + i * 256;                         // 0..511
            ra[i] = *reinterpret_cast<const float4*>(
                &A[(size_t)(bm + (idx >> 2)) * K + k0 + (idx & 3) * 4]);
        }
        #pragma unroll
        for (int i = 0; i < 2; i++) {
            int idx = tid + i * 256;
            if (TRANSB) {
                rb[i] = *reinterpret_cast<const float4*>(
                    &B[(size_t)(bn + (idx >> 2)) * K + k0 + (idx & 3) * 4]);
            } else {
                rb[i] = *reinterpret_cast<const float4*>(
                    &B[(size_t)(k0 + (idx >> 5)) * N + bn + (idx & 31) * 4]);
            }
        }
    };

    // ---- store register tile into smem buffer (with tf32 rounding) ----
    auto stage = [&](int buf) {
        #pragma unroll
        for (int i = 0; i < 2; i++) {
            int idx = tid + i * 256;
            uint4 u = make_uint4(f2tf(ra[i].x), f2tf(ra[i].y),
                                 f2tf(ra[i].z), f2tf(ra[i].w));
            *reinterpret_cast<uint4*>(
                &As[buf][(idx >> 2) * APAD + (idx & 3) * 4]) = u;
        }
        #pragma unroll
        for (int i = 0; i < 2; i++) {
            int idx = tid + i * 256;
            uint4 u = make_uint4(f2tf(rb[i].x), f2tf(rb[i].y),
                                 f2tf(rb[i].z), f2tf(rb[i].w));
            if (TRANSB) {
                *reinterpret_cast<uint4*>(
                    &Bs[buf][(idx >> 2) * APAD + (idx & 3) * 4]) = u;
            } else {
                *reinterpret_cast<uint4*>(
                    &Bs[buf][(idx >> 5) * 132 + (idx & 31) * 4]) = u;
            }
        }
    };

    const int NT = K / 16;

    fetch(0);
    stage(0);
    __syncthreads();

    for (int it = 0; it < NT; ++it) {
        const int cur = it & 1;
        const bool has_next = (it + 1 < NT);
        if (has_next) fetch((it + 1) * 16);

        // ---- compute on smem[cur]: two k8 sub-steps ----
        #pragma unroll
        for (int ks = 0; ks < 16; ks += 8) {
            uint32_t af[4][4];
            #pragma unroll
            for (int mi = 0; mi < 4; mi++) {
                const uint32_t* base =
                    &As[cur][(wm * 64 + mi * 16 + g) * APAD + ks + t];
                af[mi][0] = base[0];
                af[mi][1] = base[8 * APAD];
                af[mi][2] = base[4];
                af[mi][3] = base[8 * APAD + 4];
            }
            uint32_t bf[4][2];
            #pragma unroll
            for (int ni = 0; ni < 4; ni++) {
                if (TRANSB) {
                    const uint32_t* base =
                        &Bs[cur][(wn * 32 + ni * 8 + g) * APAD + ks + t];
                    bf[ni][0] = base[0];
                    bf[ni][1] = base[4];
                } else {
                    const uint32_t* base =
                        &Bs[cur][(ks + t) * 132 + wn * 32 + ni * 8 + g];
                    bf[ni][0] = base[0];
                    bf[ni][1] = base[4 * 132];
                }
            }
            #pragma unroll
            for (int mi = 0; mi < 4; mi++)
                #pragma unroll
                for (int ni = 0; ni < 4; ni++)
                    mma_tf32(acc[mi][ni][0], acc[mi][ni][1],
                             acc[mi][ni][2], acc[mi][ni][3],
                             af[mi][0], af[mi][1], af[mi][2], af[mi][3],
                             bf[ni][0], bf[ni][1]);
        }

        if (has_next) {
            stage(cur ^ 1);
            __syncthreads();
        }
    }

    // ---- epilogue ----
    #pragma unroll
    for (int mi = 0; mi < 4; mi++) {
        const int row = bm + wm * 64 + mi * 16 + g;
        #pragma unroll
        for (int ni = 0; ni < 4; ni++) {
            const int col = bn + wn * 32 + ni * 8 + 2 * t;
            float2 v0 = make_float2(acc[mi][ni][0] * alpha,
                                    acc[mi][ni][1] * alpha);
            float2 v1 = make_float2(acc[mi][ni][2] * alpha,
                                    acc[mi][ni][3] * alpha);
            *reinterpret_cast<float2*>(&C[(size_t)row * N + col])       = v0;
            *reinterpret_cast<float2*>(&C[(size_t)(row + 8) * N + col]) = v1;
        }
    }
}

// ---------------------------------------------------------------------------
// Row softmax over S [SEQ, SEQ], in place. One block per row, 256 threads.
// ---------------------------------------------------------------------------
__global__ void __launch_bounds__(256) softmax_kernel(float* __restrict__ S)
{
    __shared__ float red[256];
    const size_t row = blockIdx.x;
    float* p = S + row * (size_t)SEQ;
    const int t = threadIdx.x;

    float v[16];
    float m = -3.402823e38f;
    #pragma unroll
    for (int i = 0; i < 16; i++) {
        v[i] = p[t + i * 256];
        m = fmaxf(m, v[i]);
    }
    red[t] = m;
    __syncthreads();
    #pragma unroll
    for (int s = 128; s > 0; s >>= 1) {
        if (t < s) red[t] = fmaxf(red[t], red[t + s]);
        __syncthreads();
    }
    m = red[0];
    __syncthreads();

    float sum = 0.0f;
    #pragma unroll
    for (int i = 0; i < 16; i++) {
        v[i] = __expf(v[i] - m);
        sum += v[i];
    }
    red[t] = sum;
    __syncthreads();
    #pragma unroll
    for (int s = 128; s > 0; s >>= 1) {
        if (t < s) red[t] += red[t + s];
        __syncthreads();
    }
    const float inv = 1.0f / red[0];

    #pragma unroll
    for (int i = 0; i < 16; i++)
        p[t + i * 256] = v[i] * inv;
}

// ---------------------------------------------------------------------------
extern "C" void kernel_launch(void* const* d_in, const int* in_sizes, int n_in,
                              void* d_out, int out_size)
{
    const float* x  = (const float*)d_in[0];
    const float* Wq = (const float*)d_in[1];
    const float* Wk = (const float*)d_in[2];
    const float* Wv = (const float*)d_in[3];
    float* out = (float*)d_out;

    float *Q, *K, *V, *S;
    cudaGetSymbolAddress((void**)&Q, g_Q);
    cudaGetSymbolAddress((void**)&K, g_K);
    cudaGetSymbolAddress((void**)&V, g_V);
    cudaGetSymbolAddress((void**)&S, g_S);

    const dim3 blk(256);
    const dim3 gProj(EMB / 128, SEQ / 128);   // 8 x 32
    const dim3 gScore(SEQ / 128, SEQ / 128);  // 32 x 32

    // Projections: Q = x @ Wq, K = x @ Wk, V = x @ Wv
    mm_tf32<false><<<gProj, blk>>>(x, Wq, Q, SEQ, EMB, EMB, 1.0f);
    mm_tf32<false><<<gProj, blk>>>(x, Wk, K, SEQ, EMB, EMB, 1.0f);
    mm_tf32<false><<<gProj, blk>>>(x, Wv, V, SEQ, EMB, EMB, 1.0f);

    // Scores: S = (Q @ K^T) / sqrt(1024)
    mm_tf32<true><<<gScore, blk>>>(Q, K, S, SEQ, SEQ, EMB, 0.03125f);

    // Softmax rows in place
    softmax_kernel<<<SEQ, blk>>>(S);

    // Output: out = P @ V
    mm_tf32<false><<<gProj, blk>>>(S, V, out, SEQ, EMB, SEQ, 1.0f);
}

// round 4
// speedup vs baseline: 3.9112x; 2.7319x over previous
#include <cuda_runtime.h>
#include <cstdint>

#define SEQ 4096
#define EMB 1024

// ---------------- scratch (static, allocation-free) ----------------
__device__ float g_Q [(size_t)SEQ * EMB];
__device__ float g_K [(size_t)SEQ * EMB];
__device__ float g_V [(size_t)SEQ * EMB];
__device__ float g_S [(size_t)SEQ * SEQ];
__device__ float g_Xr[(size_t)SEQ * EMB];
__device__ float g_Wqt[(size_t)EMB * EMB];
__device__ float g_Wkt[(size_t)EMB * EMB];
__device__ float g_Wvt[(size_t)EMB * EMB];
__device__ float g_Vt[(size_t)EMB * SEQ];

// ---------------- helpers ----------------
__device__ __forceinline__ float f2tf32(float f) {
    uint32_t u;
    asm("cvt.rna.tf32.f32 %0, %1;" : "=r"(u) : "f"(f));
    return __uint_as_float(u);
}
__device__ __forceinline__ uint32_t smem_u32(const void* p) {
    return (uint32_t)__cvta_generic_to_shared(p);
}
__device__ __forceinline__ void cp16(uint32_t s, const void* g) {
    asm volatile("cp.async.cg.shared.global [%0], [%1], 16;" :: "r"(s), "l"(g));
}
__device__ __forceinline__ void cp_commit() {
    asm volatile("cp.async.commit_group;" ::: "memory");
}
template <int N>
__device__ __forceinline__ void cp_wait() {
    asm volatile("cp.async.wait_group %0;" :: "n"(N) : "memory");
}
__device__ __forceinline__ void mma_tf32(
    float& c0, float& c1, float& c2, float& c3,
    uint32_t a0, uint32_t a1, uint32_t a2, uint32_t a3,
    uint32_t b0, uint32_t b1)
{
    asm volatile(
        "mma.sync.aligned.m16n8k8.row.col.f32.tf32.tf32.f32 "
        "{%0,%1,%2,%3}, {%4,%5,%6,%7}, {%8,%9}, {%0,%1,%2,%3};"
        : "+f"(c0), "+f"(c1), "+f"(c2), "+f"(c3)
        : "r"(a0), "r"(a1), "r"(a2), "r"(a3), "r"(b0), "r"(b1));
}

// ---------------------------------------------------------------------------
// TF32 tensor-core NT GEMM: C[M,N] = alpha * A[M,K] @ B[N,K]^T
// Operands K-major, PRE-ROUNDED to tf32 bits. M,N mult of 128, K mult of 32.
// 256 threads (8 warps 2x4, 64x32 per warp), BK=32, 3-stage cp.async.
// Smem per operand tile: 128 rows x 32 words, XOR swizzle col^=4*(row&7)
//   -> cp.async stores and all fragment loads are bank-conflict free.
// ---------------------------------------------------------------------------
#define STG 3
#define OPW (128 * 32)                 // words per operand tile
#define STW (2 * OPW)                  // words per stage (A + B)
#define GEMM_DYNSMEM (STG * STW * 4)   // 98304 bytes

template <bool ROUND>
__global__ void __launch_bounds__(256, 2) gemm_tt(
    const float* __restrict__ A, const float* __restrict__ B,
    float* __restrict__ C, int M, int N, int K, float alpha)
{
    extern __shared__ uint32_t sm[];

    const int tid  = threadIdx.x;
    const int warp = tid >> 5;
    const int lane = tid & 31;
    const int g    = lane >> 2;     // 0..7
    const int t    = lane & 3;      // 0..3
    const int wm   = warp & 1;      // 2 warp rows x 64
    const int wn   = warp >> 1;     // 4 warp cols x 32
    const int bm   = blockIdx.y * 128;
    const int bn   = blockIdx.x * 128;

    float acc[4][4][4];
    #pragma unroll
    for (int mi = 0; mi < 4; mi++)
        #pragma unroll
        for (int ni = 0; ni < 4; ni++)
            #pragma unroll
            for (int r = 0; r < 4; r++) acc[mi][ni][r] = 0.0f;

    const uint32_t smb = smem_u32(sm);
    const int lrow = tid >> 3;          // 0..31 (4 passes -> 128 rows)
    const int lseg = tid & 7;           // 16B segment within 128B row

    auto load_stage = [&](int chunk) {
        const int s  = chunk % STG;
        const int k0 = chunk * 32;
        const uint32_t sa = smb + s * (STW * 4);
        const uint32_t sb = sa + OPW * 4;
        #pragma unroll
        for (int p = 0; p < 4; p++) {
            const int row  = lrow + p * 32;
            const int segS = lseg ^ (row & 7);             // swizzled segment
            const uint32_t so = (uint32_t)(row * 128 + segS * 16);
            const float* ga = A + (size_t)(bm + row) * K + k0 + lseg * 4;
            const float* gb = B + (size_t)(bn + row) * K + k0 + lseg * 4;
            cp16(sa + so, ga);
            cp16(sb + so, gb);
        }
        cp_commit();
    };

    const int NT = K >> 5;

    load_stage(0);
    load_stage(1);

    for (int i = 0; i < NT; i++) {
        const int s = i % STG;
        cp_wait<1>();
        __syncthreads();

        const uint32_t* As  = sm + s * STW;
        const uint32_t* Bsm = As + OPW;
        const int swz = 4 * g;                 // row&7 == g for all frag rows

        #pragma unroll
        for (int ks = 0; ks < 32; ks += 8) {
            const int c0 = (ks + t)     ^ swz;
            const int c2 = (ks + t + 4) ^ swz;

            uint32_t af[4][4];
            #pragma unroll
            for (int mi = 0; mi < 4; mi++) {
                const uint32_t* base = As + (wm * 64 + mi * 16 + g) * 32;
                af[mi][0] = base[c0];
                af[mi][1] = base[8 * 32 + c0];
                af[mi][2] = base[c2];
                af[mi][3] = base[8 * 32 + c2];
            }
            uint32_t bf[4][2];
            #pragma unroll
            for (int ni = 0; ni < 4; ni++) {
                const uint32_t* base = Bsm + (wn * 32 + ni * 8 + g) * 32;
                bf[ni][0] = base[c0];
                bf[ni][1] = base[c2];
            }
            #pragma unroll
            for (int mi = 0; mi < 4; mi++)
                #pragma unroll
                for (int ni = 0; ni < 4; ni++)
                    mma_tf32(acc[mi][ni][0], acc[mi][ni][1],
                             acc[mi][ni][2], acc[mi][ni][3],
                             af[mi][0], af[mi][1], af[mi][2], af[mi][3],
                             bf[ni][0], bf[ni][1]);
        }
        __syncthreads();

        if (i + 2 < NT) load_stage(i + 2);
        else            cp_commit();           // keep group count exact
    }

    // ---- epilogue ----
    #pragma unroll
    for (int mi = 0; mi < 4; mi++) {
        const int row = bm + wm * 64 + mi * 16 + g;
        #pragma unroll
        for (int ni = 0; ni < 4; ni++) {
            const int col = bn + wn * 32 + ni * 8 + 2 * t;
            float x0 = acc[mi][ni][0] * alpha, x1 = acc[mi][ni][1] * alpha;
            float x2 = acc[mi][ni][2] * alpha, x3 = acc[mi][ni][3] * alpha;
            if (ROUND) { x0 = f2tf32(x0); x1 = f2tf32(x1);
                         x2 = f2tf32(x2); x3 = f2tf32(x3); }
            *reinterpret_cast<float2*>(&C[(size_t)row * N + col]) =
                make_float2(x0, x1);
            *reinterpret_cast<float2*>(&C[(size_t)(row + 8) * N + col]) =
                make_float2(x2, x3);
        }
    }
}

// ---------------------------------------------------------------------------
// Elementwise tf32 rounding
// ---------------------------------------------------------------------------
__global__ void __launch_bounds__(256) round_kernel(const float* __restrict__ in,
                                                    float* __restrict__ out, int n4)
{
    int i = blockIdx.x * 256 + threadIdx.x;
    if (i < n4) {
        float4 v = reinterpret_cast<const float4*>(in)[i];
        v.x = f2tf32(v.x); v.y = f2tf32(v.y);
        v.z = f2tf32(v.z); v.w = f2tf32(v.w);
        reinterpret_cast<float4*>(out)[i] = v;
    }
}

// ---------------------------------------------------------------------------
// Tiled transpose + tf32 round: out[c*R + r] = rna(in[r*C + c])
// ---------------------------------------------------------------------------
__global__ void __launch_bounds__(256) transpose_round(const float* __restrict__ in,
                                                       float* __restrict__ out,
                                                       int R, int C)
{
    __shared__ float t[32][33];
    const int bx = blockIdx.x * 32, by = blockIdx.y * 32;
    const int x = threadIdx.x, y = threadIdx.y;     // 32 x 8
    #pragma unroll
    for (int j = 0; j < 32; j += 8)
        t[y + j][x] = in[(size_t)(by + y + j) * C + bx + x];
    __syncthreads();
    #pragma unroll
    for (int j = 0; j < 32; j += 8)
        out[(size_t)(bx + y + j) * R + by + x] = f2tf32(t[x][y + j]);
}

// ---------------------------------------------------------------------------
// Row softmax, in place, tf32-rounded output (feeds PV GEMM as operand A).
// ---------------------------------------------------------------------------
__global__ void __launch_bounds__(256) softmax_kernel(float* __restrict__ S)
{
    __shared__ float red[256];
    const size_t row = blockIdx.x;
    float* p = S + row * (size_t)SEQ;
    const int t = threadIdx.x;

    float v[16];
    float m = -3.402823e38f;
    #pragma unroll
    for (int i = 0; i < 16; i++) {
        v[i] = p[t + i * 256];
        m = fmaxf(m, v[i]);
    }
    red[t] = m;
    __syncthreads();
    #pragma unroll
    for (int s = 128; s > 0; s >>= 1) {
        if (t < s) red[t] = fmaxf(red[t], red[t + s]);
        __syncthreads();
    }
    m = red[0];
    __syncthreads();

    float sum = 0.0f;
    #pragma unroll
    for (int i = 0; i < 16; i++) {
        v[i] = __expf(v[i] - m);
        sum += v[i];
    }
    red[t] = sum;
    __syncthreads();
    #pragma unroll
    for (int s = 128; s > 0; s >>= 1) {
        if (t < s) red[t] += red[t + s];
        __syncthreads();
    }
    const float inv = 1.0f / red[0];

    #pragma unroll
    for (int i = 0; i < 16; i++)
        p[t + i * 256] = f2tf32(v[i] * inv);
}

// ---------------------------------------------------------------------------
extern "C" void kernel_launch(void* const* d_in, const int* in_sizes, int n_in,
                              void* d_out, int out_size)
{
    const float* x  = (const float*)d_in[0];
    const float* Wq = (const float*)d_in[1];
    const float* Wk = (const float*)d_in[2];
    const float* Wv = (const float*)d_in[3];
    float* out = (float*)d_out;

    float *Q, *K, *V, *S, *Xr, *Wqt, *Wkt, *Wvt, *Vt;
    cudaGetSymbolAddress((void**)&Q,  g_Q);
    cudaGetSymbolAddress((void**)&K,  g_K);
    cudaGetSymbolAddress((void**)&V,  g_V);
    cudaGetSymbolAddress((void**)&S,  g_S);
    cudaGetSymbolAddress((void**)&Xr, g_Xr);
    cudaGetSymbolAddress((void**)&Wqt, g_Wqt);
    cudaGetSymbolAddress((void**)&Wkt, g_Wkt);
    cudaGetSymbolAddress((void**)&Wvt, g_Wvt);
    cudaGetSymbolAddress((void**)&Vt, g_Vt);

    cudaFuncSetAttribute(gemm_tt<true>,
        cudaFuncAttributeMaxDynamicSharedMemorySize, GEMM_DYNSMEM);
    cudaFuncSetAttribute(gemm_tt<false>,
        cudaFuncAttributeMaxDynamicSharedMemorySize, GEMM_DYNSMEM);

    const dim3 tblk(32, 8);
    const dim3 gW(EMB / 32, EMB / 32);
    const dim3 gVt(EMB / 32, SEQ / 32);

    // Operand prep: round x; transpose+round weights (all become K-major NT B).
    round_kernel<<<(SEQ * EMB / 4 + 255) / 256, 256>>>(x, Xr, SEQ * EMB / 4);
    transpose_round<<<gW, tblk>>>(Wq, Wqt, EMB, EMB);
    transpose_round<<<gW, tblk>>>(Wk, Wkt, EMB, EMB);
    transpose_round<<<gW, tblk>>>(Wv, Wvt, EMB, EMB);

    const dim3 blk(256);
    const dim3 gProj(EMB / 128, SEQ / 128);    // 8 x 32
    const dim3 gScore(SEQ / 128, SEQ / 128);   // 32 x 32

    // Projections (NT): Q/K epilogue-rounded (they feed the score GEMM).
    gemm_tt<true ><<<gProj, blk, GEMM_DYNSMEM>>>(Xr, Wqt, Q, SEQ, EMB, EMB, 1.0f);
    gemm_tt<true ><<<gProj, blk, GEMM_DYNSMEM>>>(Xr, Wkt, K, SEQ, EMB, EMB, 1.0f);
    gemm_tt<false><<<gProj, blk, GEMM_DYNSMEM>>>(Xr, Wvt, V, SEQ, EMB, EMB, 1.0f);

    // V^T (rounded) for the NT PV GEMM.
    transpose_round<<<gVt, tblk>>>(V, Vt, SEQ, EMB);

    // Scores: S = (Q @ K^T) / 32.
    gemm_tt<false><<<gScore, blk, GEMM_DYNSMEM>>>(Q, K, S, SEQ, SEQ, EMB, 0.03125f);

    // Softmax rows (rounds P to tf32).
    softmax_kernel<<<SEQ, 256>>>(S);

    // Output: out = P @ Vt^T.
    gemm_tt<false><<<gProj, blk, GEMM_DYNSMEM>>>(S, Vt, out, SEQ, EMB, SEQ, 1.0f);
}

// round 5
// speedup vs baseline: 4.1456x; 1.0599x over previous
#include <cuda_runtime.h>
#include <cstdint>

#define SEQ 4096
#define EMB 1024

// ---------------- scratch (static, allocation-free) ----------------
__device__ float g_Q [(size_t)SEQ * EMB];
__device__ float g_K [(size_t)SEQ * EMB];
__device__ float g_V [(size_t)SEQ * EMB];
__device__ float g_S [(size_t)SEQ * SEQ];
__device__ float g_Xr[(size_t)SEQ * EMB];
__device__ float g_Wqt[(size_t)EMB * EMB];
__device__ float g_Wkt[(size_t)EMB * EMB];
__device__ float g_Wvt[(size_t)EMB * EMB];
__device__ float g_Vt[(size_t)EMB * SEQ];
__device__ float g_rsum[SEQ];

// ---------------- helpers ----------------
__device__ __forceinline__ float f2tf32(float f) {
    uint32_t u;
    asm("cvt.rna.tf32.f32 %0, %1;" : "=r"(u) : "f"(f));
    return __uint_as_float(u);
}
__device__ __forceinline__ uint32_t smem_u32(const void* p) {
    return (uint32_t)__cvta_generic_to_shared(p);
}
__device__ __forceinline__ void cp16(uint32_t s, const void* g) {
    asm volatile("cp.async.cg.shared.global [%0], [%1], 16;" :: "r"(s), "l"(g));
}
__device__ __forceinline__ void cp_commit() {
    asm volatile("cp.async.commit_group;" ::: "memory");
}
template <int N>
__device__ __forceinline__ void cp_wait() {
    asm volatile("cp.async.wait_group %0;" :: "n"(N) : "memory");
}
__device__ __forceinline__ float ex2f(float y) {
    float r;
    asm("ex2.approx.ftz.f32 %0, %1;" : "=f"(r) : "f"(y));
    return r;
}
__device__ __forceinline__ void mma_tf32(
    float& c0, float& c1, float& c2, float& c3,
    uint32_t a0, uint32_t a1, uint32_t a2, uint32_t a3,
    uint32_t b0, uint32_t b1)
{
    asm volatile(
        "mma.sync.aligned.m16n8k8.row.col.f32.tf32.tf32.f32 "
        "{%0,%1,%2,%3}, {%4,%5,%6,%7}, {%8,%9}, {%0,%1,%2,%3};"
        : "+f"(c0), "+f"(c1), "+f"(c2), "+f"(c3)
        : "r"(a0), "r"(a1), "r"(a2), "r"(a3), "r"(b0), "r"(b1));
}

// ---------------------------------------------------------------------------
// TF32 tensor-core NT GEMM body: C[M,N] = alpha * A[M,K] @ B[N,K]^T
// Operands K-major, PRE-ROUNDED to tf32 bits. M,N mult of 128, K mult of 32.
// 256 threads (8 warps 2x4, 64x32/warp), BK=32, 3-stage cp.async,
// ONE __syncthreads per k-iteration (3 buffers, distance-2 prefetch).
// Optional epilogue: tf32-round output; per-row reciprocal-sum scaling.
// ---------------------------------------------------------------------------
#define STG 3
#define OPW (128 * 32)                 // words per operand tile
#define STW (2 * OPW)                  // words per stage (A + B)
#define GEMM_DYNSMEM (STG * STW * 4)   // 98304 bytes

__device__ __forceinline__ void gemm_body(
    const float* __restrict__ A, const float* __restrict__ B,
    float* __restrict__ C, int N, int K, float alpha,
    bool round_out, const float* __restrict__ rscale,
    int bm, int bn)
{
    extern __shared__ uint32_t sm[];

    const int tid  = threadIdx.x;
    const int warp = tid >> 5;
    const int lane = tid & 31;
    const int g    = lane >> 2;
    const int t    = lane & 3;
    const int wm   = warp & 1;
    const int wn   = warp >> 1;

    float acc[4][4][4];
    #pragma unroll
    for (int mi = 0; mi < 4; mi++)
        #pragma unroll
        for (int ni = 0; ni < 4; ni++)
            #pragma unroll
            for (int r = 0; r < 4; r++) acc[mi][ni][r] = 0.0f;

    const uint32_t smb = smem_u32(sm);
    const int lrow = tid >> 3;
    const int lseg = tid & 7;

    auto load_stage = [&](int chunk) {
        const int s  = chunk % STG;
        const int k0 = chunk * 32;
        const uint32_t sa = smb + s * (STW * 4);
        const uint32_t sb = sa + OPW * 4;
        #pragma unroll
        for (int p = 0; p < 4; p++) {
            const int row  = lrow + p * 32;
            const int segS = lseg ^ (row & 7);
            const uint32_t so = (uint32_t)(row * 128 + segS * 16);
            cp16(sa + so, A + (size_t)(bm + row) * K + k0 + lseg * 4);
            cp16(sb + so, B + (size_t)(bn + row) * K + k0 + lseg * 4);
        }
        cp_commit();
    };

    const int NT = K >> 5;

    load_stage(0);
    load_stage(1);

    for (int i = 0; i < NT; i++) {
        const int s = i % STG;
        cp_wait<1>();
        __syncthreads();

        if (i + 2 < NT) load_stage(i + 2);
        else            cp_commit();           // keep group count exact

        const uint32_t* As  = sm + s * STW;
        const uint32_t* Bsm = As + OPW;
        const int swz = 4 * g;

        #pragma unroll
        for (int ks = 0; ks < 32; ks += 8) {
            const int c0 = (ks + t)     ^ swz;
            const int c2 = (ks + t + 4) ^ swz;

            uint32_t af[4][4];
            #pragma unroll
            for (int mi = 0; mi < 4; mi++) {
                const uint32_t* base = As + (wm * 64 + mi * 16 + g) * 32;
                af[mi][0] = base[c0];
                af[mi][1] = base[8 * 32 + c0];
                af[mi][2] = base[c2];
                af[mi][3] = base[8 * 32 + c2];
            }
            uint32_t bf[4][2];
            #pragma unroll
            for (int ni = 0; ni < 4; ni++) {
                const uint32_t* base = Bsm + (wn * 32 + ni * 8 + g) * 32;
                bf[ni][0] = base[c0];
                bf[ni][1] = base[c2];
            }
            #pragma unroll
            for (int mi = 0; mi < 4; mi++)
                #pragma unroll
                for (int ni = 0; ni < 4; ni++)
                    mma_tf32(acc[mi][ni][0], acc[mi][ni][1],
                             acc[mi][ni][2], acc[mi][ni][3],
                             af[mi][0], af[mi][1], af[mi][2], af[mi][3],
                             bf[ni][0], bf[ni][1]);
        }
    }

    // ---- epilogue ----
    #pragma unroll
    for (int mi = 0; mi < 4; mi++) {
        const int row = bm + wm * 64 + mi * 16 + g;
        float s0 = alpha, s1 = alpha;
        if (rscale) {
            s0 = alpha * __ldg(&rscale[row]);
            s1 = alpha * __ldg(&rscale[row + 8]);
        }
        #pragma unroll
        for (int ni = 0; ni < 4; ni++) {
            const int col = bn + wn * 32 + ni * 8 + 2 * t;
            float x0 = acc[mi][ni][0] * s0, x1 = acc[mi][ni][1] * s0;
            float x2 = acc[mi][ni][2] * s1, x3 = acc[mi][ni][3] * s1;
            if (round_out) { x0 = f2tf32(x0); x1 = f2tf32(x1);
                             x2 = f2tf32(x2); x3 = f2tf32(x3); }
            *reinterpret_cast<float2*>(&C[(size_t)row * N + col]) =
                make_float2(x0, x1);
            *reinterpret_cast<float2*>(&C[(size_t)(row + 8) * N + col]) =
                make_float2(x2, x3);
        }
    }
}

__global__ void __launch_bounds__(256, 2) gemm_k(
    const float* __restrict__ A, const float* __restrict__ B,
    float* __restrict__ C, int N, int K, float alpha,
    int round_out, const float* __restrict__ rscale)
{
    gemm_body(A, B, C, N, K, alpha, round_out != 0, rscale,
              blockIdx.y * 128, blockIdx.x * 128);
}

// Fused Q/K/V projections: blockIdx.z selects weight/output.
__global__ void __launch_bounds__(256, 2) proj_k(
    const float* __restrict__ Xr,
    const float* __restrict__ B0, const float* __restrict__ B1,
    const float* __restrict__ B2,
    float* __restrict__ C0, float* __restrict__ C1, float* __restrict__ C2)
{
    const int z = blockIdx.z;
    const float* B = (z == 0) ? B0 : (z == 1) ? B1 : B2;
    float*       C = (z == 0) ? C0 : (z == 1) ? C1 : C2;
    gemm_body(Xr, B, C, EMB, EMB, 1.0f, z < 2, nullptr,
              blockIdx.y * 128, blockIdx.x * 128);
}

// ---------------------------------------------------------------------------
// Elementwise tf32 rounding
// ---------------------------------------------------------------------------
__global__ void __launch_bounds__(256) round_kernel(const float* __restrict__ in,
                                                    float* __restrict__ out, int n4)
{
    int i = blockIdx.x * 256 + threadIdx.x;
    if (i < n4) {
        float4 v = reinterpret_cast<const float4*>(in)[i];
        v.x = f2tf32(v.x); v.y = f2tf32(v.y);
        v.z = f2tf32(v.z); v.w = f2tf32(v.w);
        reinterpret_cast<float4*>(out)[i] = v;
    }
}

// ---------------------------------------------------------------------------
// Tiled transpose + tf32 round: out[c*R + r] = rna(in[r*C + c])
// ---------------------------------------------------------------------------
__device__ __forceinline__ void transpose_body(const float* __restrict__ in,
                                               float* __restrict__ out,
                                               int R, int C)
{
    __shared__ float t[32][33];
    const int bx = blockIdx.x * 32, by = blockIdx.y * 32;
    const int x = threadIdx.x, y = threadIdx.y;     // 32 x 8
    #pragma unroll
    for (int j = 0; j < 32; j += 8)
        t[y + j][x] = in[(size_t)(by + y + j) * C + bx + x];
    __syncthreads();
    #pragma unroll
    for (int j = 0; j < 32; j += 8)
        out[(size_t)(bx + y + j) * R + by + x] = f2tf32(t[x][y + j]);
}

__global__ void __launch_bounds__(256) transpose_round(const float* __restrict__ in,
                                                       float* __restrict__ out,
                                                       int R, int C)
{
    transpose_body(in, out, R, C);
}

// Fused transpose of the 3 weight matrices (blockIdx.z selects).
__global__ void __launch_bounds__(256) wtrans_k(
    const float* __restrict__ Wq, const float* __restrict__ Wk,
    const float* __restrict__ Wv,
    float* __restrict__ Tq, float* __restrict__ Tk, float* __restrict__ Tv)
{
    const int z = blockIdx.z;
    const float* in = (z == 0) ? Wq : (z == 1) ? Wk : Wv;
    float*      out = (z == 0) ? Tq : (z == 1) ? Tk : Tv;
    transpose_body(in, out, EMB, EMB);
}

// ---------------------------------------------------------------------------
// Row exp (no max, no normalize): S <- tf32(exp(S)); rsum[row] <- sum.
// Hybrid exp: 8 elems via MUFU ex2, 8 via FMA-pipe exp2 polynomial.
// Normalization (1/rsum) is applied in the PV-GEMM epilogue.
// ---------------------------------------------------------------------------
__global__ void __launch_bounds__(256) softexp_kernel(float* __restrict__ S,
                                                      float* __restrict__ rsum)
{
    __shared__ float red[8];
    const size_t row = blockIdx.x;
    float* p = S + row * (size_t)SEQ;
    const int t = threadIdx.x;
    const int lane = t & 31, warp = t >> 5;

    const float LOG2E = 1.4426950408889634f;
    const float MAGIC = 12582912.0f;          // 1.5 * 2^23

    float v[16];
    #pragma unroll
    for (int i = 0; i < 16; i++) v[i] = p[t + i * 256];

    float sum = 0.0f;

    // 8 elements on the MUFU pipe
    #pragma unroll
    for (int i = 0; i < 8; i++) {
        v[i] = ex2f(v[i] * LOG2E);
        sum += v[i];
    }
    // 8 elements on the FMA pipe: 2^y = 2^n * poly(f), y = n + f, f in [-.5,.5]
    #pragma unroll
    for (int i = 8; i < 16; i++) {
        float y  = v[i] * LOG2E;
        float tm = __fadd_rn(y, MAGIC);
        float f  = __fadd_rn(y, -__fadd_rn(tm, -MAGIC));
        int   eb = (__float_as_int(tm) << 23) + 0x3F800000;
        float pl = 0.0013333558f;
        pl = fmaf(pl, f, 0.0096181291f);
        pl = fmaf(pl, f, 0.0555041087f);
        pl = fmaf(pl, f, 0.2402265069f);
        pl = fmaf(pl, f, 0.6931471806f);
        pl = fmaf(pl, f, 1.0f);
        v[i] = __int_as_float(eb) * pl;
        sum += v[i];
    }

    #pragma unroll
    for (int i = 0; i < 16; i++) p[t + i * 256] = f2tf32(v[i]);

    // block reduction of sum -> rsum[row] (stored as reciprocal)
    #pragma unroll
    for (int s = 16; s > 0; s >>= 1)
        sum += __shfl_xor_sync(0xFFFFFFFF, sum, s);
    if (lane == 0) red[warp] = sum;
    __syncthreads();
    if (warp == 0) {
        float w = (lane < 8) ? red[lane] : 0.0f;
        #pragma unroll
        for (int s = 4; s > 0; s >>= 1)
            w += __shfl_xor_sync(0xFFFFFFFF, w, s);
        if (lane == 0) rsum[row] = 1.0f / w;
    }
}

// ---------------------------------------------------------------------------
extern "C" void kernel_launch(void* const* d_in, const int* in_sizes, int n_in,
                              void* d_out, int out_size)
{
    const float* x  = (const float*)d_in[0];
    const float* Wq = (const float*)d_in[1];
    const float* Wk = (const float*)d_in[2];
    const float* Wv = (const float*)d_in[3];
    float* out = (float*)d_out;

    float *Q, *K, *V, *S, *Xr, *Wqt, *Wkt, *Wvt, *Vt, *Rs;
    cudaGetSymbolAddress((void**)&Q,  g_Q);
    cudaGetSymbolAddress((void**)&K,  g_K);
    cudaGetSymbolAddress((void**)&V,  g_V);
    cudaGetSymbolAddress((void**)&S,  g_S);
    cudaGetSymbolAddress((void**)&Xr, g_Xr);
    cudaGetSymbolAddress((void**)&Wqt, g_Wqt);
    cudaGetSymbolAddress((void**)&Wkt, g_Wkt);
    cudaGetSymbolAddress((void**)&Wvt, g_Wvt);
    cudaGetSymbolAddress((void**)&Vt, g_Vt);
    cudaGetSymbolAddress((void**)&Rs, g_rsum);

    cudaFuncSetAttribute(gemm_k,
        cudaFuncAttributeMaxDynamicSharedMemorySize, GEMM_DYNSMEM);
    cudaFuncSetAttribute(proj_k,
        cudaFuncAttributeMaxDynamicSharedMemorySize, GEMM_DYNSMEM);

    const dim3 tblk(32, 8);
    const dim3 gW(EMB / 32, EMB / 32, 3);
    const dim3 gVt(EMB / 32, SEQ / 32);

    // Operand prep.
    round_kernel<<<(SEQ * EMB / 4 + 255) / 256, 256>>>(x, Xr, SEQ * EMB / 4);
    wtrans_k<<<gW, tblk>>>(Wq, Wk, Wv, Wqt, Wkt, Wvt);

    const dim3 blk(256);
    const dim3 gProj(EMB / 128, SEQ / 128, 3);  // fused Q/K/V projections
    const dim3 gOne (EMB / 128, SEQ / 128);
    const dim3 gScore(SEQ / 128, SEQ / 128);

    proj_k<<<gProj, blk, GEMM_DYNSMEM>>>(Xr, Wqt, Wkt, Wvt, Q, K, V);

    // V^T (rounded) for the NT PV GEMM.
    transpose_round<<<gVt, tblk>>>(V, Vt, SEQ, EMB);

    // Scores: S = (Q @ K^T) / 32.
    gemm_k<<<gScore, blk, GEMM_DYNSMEM>>>(Q, K, S, SEQ, EMB, 0.03125f, 0, nullptr);

    // Unnormalized exp + row sums.
    softexp_kernel<<<SEQ, 256>>>(S, Rs);

    // Output: out = diag(1/rowsum) * (expS @ Vt^T).
    gemm_k<<<gOne, blk, GEMM_DYNSMEM>>>(S, Vt, out, EMB, SEQ, 1.0f, 0, Rs);
}

// round 6
// speedup vs baseline: 7.4928x; 1.8074x over previous
#include <cuda_runtime.h>
#include <cuda_fp16.h>
#include <cstdint>

#define SEQ 4096
#define EMB 1024

// ---------------- scratch (static, allocation-free) ----------------
__device__ __half g_Xh [(size_t)SEQ * EMB];
__device__ __half g_Wqt[(size_t)EMB * EMB];
__device__ __half g_Wkt[(size_t)EMB * EMB];
__device__ __half g_Wvt[(size_t)EMB * EMB];
__device__ __half g_Qh [(size_t)SEQ * EMB];
__device__ __half g_Kh [(size_t)SEQ * EMB];
__device__ __half g_Vh [(size_t)SEQ * EMB];
__device__ __half g_Vt [(size_t)EMB * SEQ];
__device__ float  g_S  [(size_t)SEQ * SEQ];
__device__ __half g_Sh [(size_t)SEQ * SEQ];
__device__ float  g_rsum[SEQ];

// ---------------- helpers ----------------
__device__ __forceinline__ uint32_t smem_u32(const void* p) {
    return (uint32_t)__cvta_generic_to_shared(p);
}
__device__ __forceinline__ void cp16(uint32_t s, const void* g) {
    asm volatile("cp.async.cg.shared.global [%0], [%1], 16;" :: "r"(s), "l"(g));
}
__device__ __forceinline__ void cp_commit() {
    asm volatile("cp.async.commit_group;" ::: "memory");
}
template <int N>
__device__ __forceinline__ void cp_wait() {
    asm volatile("cp.async.wait_group %0;" :: "n"(N) : "memory");
}
__device__ __forceinline__ float ex2f(float y) {
    float r;
    asm("ex2.approx.ftz.f32 %0, %1;" : "=f"(r) : "f"(y));
    return r;
}
// m16n8k16 fp16 MMA, fp32 accumulate
__device__ __forceinline__ void mma_f16(
    float& c0, float& c1, float& c2, float& c3,
    uint32_t a0, uint32_t a1, uint32_t a2, uint32_t a3,
    uint32_t b0, uint32_t b1)
{
    asm volatile(
        "mma.sync.aligned.m16n8k16.row.col.f32.f16.f16.f32 "
        "{%0,%1,%2,%3}, {%4,%5,%6,%7}, {%8,%9}, {%0,%1,%2,%3};"
        : "+f"(c0), "+f"(c1), "+f"(c2), "+f"(c3)
        : "r"(a0), "r"(a1), "r"(a2), "r"(a3), "r"(b0), "r"(b1));
}

// ---------------------------------------------------------------------------
// FP16 tensor-core NT GEMM: C[M,N] = scale * A[M,K] @ B[N,K]^T
// A,B fp16 K-major. M,N mult of 128, K mult of 64. fp32 accumulation.
// 256 threads (8 warps 2x4, 64x32/warp), BK=64 (128B rows), 3-stage cp.async,
// one __syncthreads per iter. Smem tile: 128 rows x 32 fp16x2-words,
// XOR swizzle wordcol ^= 4*(row&7) -> conflict-free stores & fragment loads.
// ---------------------------------------------------------------------------
#define STG 3
#define OPW (128 * 32)                 // fp16x2 words per operand tile (16KB)
#define STW (2 * OPW)
#define GEMM_DYNSMEM (STG * STW * 4)   // 98304 bytes

template <typename OutT>
__device__ __forceinline__ void gemm_body(
    const __half* __restrict__ A, const __half* __restrict__ B,
    OutT* __restrict__ C, int N, int K, float alpha,
    const float* __restrict__ rscale, int bm, int bn)
{
    extern __shared__ uint32_t sm[];

    const int tid  = threadIdx.x;
    const int warp = tid >> 5;
    const int lane = tid & 31;
    const int g    = lane >> 2;
    const int t    = lane & 3;
    const int wm   = warp & 1;
    const int wn   = warp >> 1;

    float acc[4][4][4];
    #pragma unroll
    for (int mi = 0; mi < 4; mi++)
        #pragma unroll
        for (int ni = 0; ni < 4; ni++)
            #pragma unroll
            for (int r = 0; r < 4; r++) acc[mi][ni][r] = 0.0f;

    const uint32_t smb = smem_u32(sm);
    const int lrow = tid >> 3;          // 0..31, 4 passes -> 128 rows
    const int lseg = tid & 7;           // 16B segment (8 halfs) in 128B row

    auto load_stage = [&](int chunk) {
        const int s  = chunk % STG;
        const int k0 = chunk * 64;
        const uint32_t sa = smb + s * (STW * 4);
        const uint32_t sb = sa + OPW * 4;
        #pragma unroll
        for (int p = 0; p < 4; p++) {
            const int row  = lrow + p * 32;
            const int segS = lseg ^ (row & 7);
            const uint32_t so = (uint32_t)(row * 128 + segS * 16);
            cp16(sa + so, A + (size_t)(bm + row) * K + k0 + lseg * 8);
            cp16(sb + so, B + (size_t)(bn + row) * K + k0 + lseg * 8);
        }
        cp_commit();
    };

    const int NT = K >> 6;

    load_stage(0);
    load_stage(1);

    for (int i = 0; i < NT; i++) {
        const int s = i % STG;
        cp_wait<1>();
        __syncthreads();

        if (i + 2 < NT) load_stage(i + 2);
        else            cp_commit();           // keep group count exact

        const uint32_t* As  = sm + s * STW;
        const uint32_t* Bsm = As + OPW;
        const int swz = 4 * g;

        #pragma unroll
        for (int ksi = 0; ksi < 4; ksi++) {    // 4 x k16 within BK=64
            const int c0 = (ksi * 8 + t)     ^ swz;
            const int c2 = (ksi * 8 + t + 4) ^ swz;

            uint32_t af[4][4];
            #pragma unroll
            for (int mi = 0; mi < 4; mi++) {
                const uint32_t* base = As + (wm * 64 + mi * 16 + g) * 32;
                af[mi][0] = base[c0];
                af[mi][1] = base[8 * 32 + c0];
                af[mi][2] = base[c2];
                af[mi][3] = base[8 * 32 + c2];
            }
            uint32_t bf[4][2];
            #pragma unroll
            for (int ni = 0; ni < 4; ni++) {
                const uint32_t* base = Bsm + (wn * 32 + ni * 8 + g) * 32;
                bf[ni][0] = base[c0];
                bf[ni][1] = base[c2];
            }
            #pragma unroll
            for (int mi = 0; mi < 4; mi++)
                #pragma unroll
                for (int ni = 0; ni < 4; ni++)
                    mma_f16(acc[mi][ni][0], acc[mi][ni][1],
                            acc[mi][ni][2], acc[mi][ni][3],
                            af[mi][0], af[mi][1], af[mi][2], af[mi][3],
                            bf[ni][0], bf[ni][1]);
        }
    }

    // ---- epilogue ----
    #pragma unroll
    for (int mi = 0; mi < 4; mi++) {
        const int row = bm + wm * 64 + mi * 16 + g;
        float s0 = alpha, s1 = alpha;
        if (rscale) {
            s0 = alpha * __ldg(&rscale[row]);
            s1 = alpha * __ldg(&rscale[row + 8]);
        }
        #pragma unroll
        for (int ni = 0; ni < 4; ni++) {
            const int col = bn + wn * 32 + ni * 8 + 2 * t;
            const float x0 = acc[mi][ni][0] * s0, x1 = acc[mi][ni][1] * s0;
            const float x2 = acc[mi][ni][2] * s1, x3 = acc[mi][ni][3] * s1;
            if constexpr (sizeof(OutT) == 2) {
                *reinterpret_cast<__half2*>(&C[(size_t)row * N + col]) =
                    __floats2half2_rn(x0, x1);
                *reinterpret_cast<__half2*>(&C[(size_t)(row + 8) * N + col]) =
                    __floats2half2_rn(x2, x3);
            } else {
                *reinterpret_cast<float2*>(&C[(size_t)row * N + col]) =
                    make_float2(x0, x1);
                *reinterpret_cast<float2*>(&C[(size_t)(row + 8) * N + col]) =
                    make_float2(x2, x3);
            }
        }
    }
}

// fp32-output GEMM (score / PV)
__global__ void __launch_bounds__(256, 2) gemm_f32_k(
    const __half* __restrict__ A, const __half* __restrict__ B,
    float* __restrict__ C, int N, int K, float alpha,
    const float* __restrict__ rscale)
{
    gemm_body<float>(A, B, C, N, K, alpha, rscale,
                     blockIdx.y * 128, blockIdx.x * 128);
}

// Fused Q/K/V projections, fp16 output: blockIdx.z selects weight/output.
__global__ void __launch_bounds__(256, 2) proj_k(
    const __half* __restrict__ Xh,
    const __half* __restrict__ B0, const __half* __restrict__ B1,
    const __half* __restrict__ B2,
    __half* __restrict__ C0, __half* __restrict__ C1, __half* __restrict__ C2)
{
    const int z = blockIdx.z;
    const __half* B = (z == 0) ? B0 : (z == 1) ? B1 : B2;
    __half*       C = (z == 0) ? C0 : (z == 1) ? C1 : C2;
    gemm_body<__half>(Xh, B, C, EMB, EMB, 1.0f, nullptr,
                      blockIdx.y * 128, blockIdx.x * 128);
}

// ---------------------------------------------------------------------------
// x fp32 -> fp16
// ---------------------------------------------------------------------------
__global__ void __launch_bounds__(256) cvtx_kernel(const float* __restrict__ in,
                                                   __half* __restrict__ out, int n4)
{
    int i = blockIdx.x * 256 + threadIdx.x;
    if (i < n4) {
        float4 v = reinterpret_cast<const float4*>(in)[i];
        __half2* o = reinterpret_cast<__half2*>(out) + i * 2;
        o[0] = __floats2half2_rn(v.x, v.y);
        o[1] = __floats2half2_rn(v.z, v.w);
    }
}

// ---------------------------------------------------------------------------
// Fused transpose of the 3 fp32 weight matrices -> fp16 (blockIdx.z selects).
// ---------------------------------------------------------------------------
__global__ void __launch_bounds__(256) wtrans_k(
    const float* __restrict__ Wq, const float* __restrict__ Wk,
    const float* __restrict__ Wv,
    __half* __restrict__ Tq, __half* __restrict__ Tk, __half* __restrict__ Tv)
{
    __shared__ float t[32][33];
    const int z = blockIdx.z;
    const float* in = (z == 0) ? Wq : (z == 1) ? Wk : Wv;
    __half*     out = (z == 0) ? Tq : (z == 1) ? Tk : Tv;

    const int bx = blockIdx.x * 32, by = blockIdx.y * 32;
    const int x = threadIdx.x, y = threadIdx.y;     // 32 x 8
    #pragma unroll
    for (int j = 0; j < 32; j += 8)
        t[y + j][x] = in[(size_t)(by + y + j) * EMB + bx + x];
    __syncthreads();
    #pragma unroll
    for (int j = 0; j < 32; j += 8)
        out[(size_t)(bx + y + j) * EMB + by + x] = __float2half(t[x][y + j]);
}

// ---------------------------------------------------------------------------
// fp16 transpose (V -> V^T)
// ---------------------------------------------------------------------------
__global__ void __launch_bounds__(256) htrans_k(const __half* __restrict__ in,
                                                __half* __restrict__ out,
                                                int R, int C)
{
    __shared__ __half t[32][34];
    const int bx = blockIdx.x * 32, by = blockIdx.y * 32;
    const int x = threadIdx.x, y = threadIdx.y;     // 32 x 8
    #pragma unroll
    for (int j = 0; j < 32; j += 8)
        t[y + j][x] = in[(size_t)(by + y + j) * C + bx + x];
    __syncthreads();
    #pragma unroll
    for (int j = 0; j < 32; j += 8)
        out[(size_t)(bx + y + j) * R + by + x] = t[x][y + j];
}

// ---------------------------------------------------------------------------
// Row exp (no max, no normalize): Sh <- fp16(exp(S)); rsum[row] <- 1/sum.
// Hybrid exp: 8 elems via MUFU ex2, 8 via FMA-pipe exp2 polynomial.
// Normalization (1/rsum) is applied in the PV-GEMM epilogue.
// ---------------------------------------------------------------------------
__global__ void __launch_bounds__(256) softexp_kernel(const float* __restrict__ S,
                                                      __half* __restrict__ Sh,
                                                      float* __restrict__ rsum)
{
    __shared__ float red[8];
    const size_t row = blockIdx.x;
    const float* p = S + row * (size_t)SEQ;
    __half* ph = Sh + row * (size_t)SEQ;
    const int t = threadIdx.x;
    const int lane = t & 31, warp = t >> 5;

    const float LOG2E = 1.4426950408889634f;
    const float MAGIC = 12582912.0f;          // 1.5 * 2^23

    float v[16];
    #pragma unroll
    for (int i = 0; i < 16; i++) v[i] = p[t + i * 256];

    float sum = 0.0f;

    // 8 elements on the MUFU pipe
    #pragma unroll
    for (int i = 0; i < 8; i++) {
        v[i] = ex2f(v[i] * LOG2E);
        sum += v[i];
    }
    // 8 elements on the FMA pipe: 2^y = 2^n * poly(f)
    #pragma unroll
    for (int i = 8; i < 16; i++) {
        float y  = v[i] * LOG2E;
        float tm = __fadd_rn(y, MAGIC);
        float f  = __fadd_rn(y, -__fadd_rn(tm, -MAGIC));
        int   eb = (__float_as_int(tm) << 23) + 0x3F800000;
        float pl = 0.0013333558f;
        pl = fmaf(pl, f, 0.0096181291f);
        pl = fmaf(pl, f, 0.0555041087f);
        pl = fmaf(pl, f, 0.2402265069f);
        pl = fmaf(pl, f, 0.6931471806f);
        pl = fmaf(pl, f, 1.0f);
        v[i] = __int_as_float(eb) * pl;
        sum += v[i];
    }

    #pragma unroll
    for (int i = 0; i < 16; i++) ph[t + i * 256] = __float2half(v[i]);

    // block reduction of sum -> rsum[row] (stored as reciprocal)
    #pragma unroll
    for (int s = 16; s > 0; s >>= 1)
        sum += __shfl_xor_sync(0xFFFFFFFF, sum, s);
    if (lane == 0) red[warp] = sum;
    __syncthreads();
    if (warp == 0) {
        float w = (lane < 8) ? red[lane] : 0.0f;
        #pragma unroll
        for (int s = 4; s > 0; s >>= 1)
            w += __shfl_xor_sync(0xFFFFFFFF, w, s);
        if (lane == 0) rsum[row] = 1.0f / w;
    }
}

// ---------------------------------------------------------------------------
extern "C" void kernel_launch(void* const* d_in, const int* in_sizes, int n_in,
                              void* d_out, int out_size)
{
    const float* x  = (const float*)d_in[0];
    const float* Wq = (const float*)d_in[1];
    const float* Wk = (const float*)d_in[2];
    const float* Wv = (const float*)d_in[3];
    float* out = (float*)d_out;

    __half *Xh, *Wqt, *Wkt, *Wvt, *Qh, *Kh, *Vh, *Vt, *Sh;
    float *S, *Rs;
    cudaGetSymbolAddress((void**)&Xh,  g_Xh);
    cudaGetSymbolAddress((void**)&Wqt, g_Wqt);
    cudaGetSymbolAddress((void**)&Wkt, g_Wkt);
    cudaGetSymbolAddress((void**)&Wvt, g_Wvt);
    cudaGetSymbolAddress((void**)&Qh,  g_Qh);
    cudaGetSymbolAddress((void**)&Kh,  g_Kh);
    cudaGetSymbolAddress((void**)&Vh,  g_Vh);
    cudaGetSymbolAddress((void**)&Vt,  g_Vt);
    cudaGetSymbolAddress((void**)&S,   g_S);
    cudaGetSymbolAddress((void**)&Sh,  g_Sh);
    cudaGetSymbolAddress((void**)&Rs,  g_rsum);

    cudaFuncSetAttribute(gemm_f32_k,
        cudaFuncAttributeMaxDynamicSharedMemorySize, GEMM_DYNSMEM);
    cudaFuncSetAttribute(proj_k,
        cudaFuncAttributeMaxDynamicSharedMemorySize, GEMM_DYNSMEM);

    const dim3 tblk(32, 8);
    const dim3 gW(EMB / 32, EMB / 32, 3);
    const dim3 gVt(EMB / 32, SEQ / 32);

    // Operand prep.
    cvtx_kernel<<<(SEQ * EMB / 4 + 255) / 256, 256>>>(x, Xh, SEQ * EMB / 4);
    wtrans_k<<<gW, tblk>>>(Wq, Wk, Wv, Wqt, Wkt, Wvt);

    const dim3 blk(256);
    const dim3 gProj(EMB / 128, SEQ / 128, 3);
    const dim3 gOne (EMB / 128, SEQ / 128);
    const dim3 gScore(SEQ / 128, SEQ / 128);

    // Projections (NT, fp16 out).
    proj_k<<<gProj, blk, GEMM_DYNSMEM>>>(Xh, Wqt, Wkt, Wvt, Qh, Kh, Vh);

    // V^T for the NT PV GEMM.
    htrans_k<<<gVt, tblk>>>(Vh, Vt, SEQ, EMB);

    // Scores: S = (Q @ K^T) / 32  (fp32 out).
    gemm_f32_k<<<gScore, blk, GEMM_DYNSMEM>>>(Qh, Kh, S, SEQ, EMB, 0.03125f, nullptr);

    // Unnormalized exp (fp16 out) + reciprocal row sums.
    softexp_kernel<<<SEQ, 256>>>(S, Sh, Rs);

    // Output: out = diag(1/rowsum) * (expS @ Vt^T)  (fp32 out).
    gemm_f32_k<<<gOne, blk, GEMM_DYNSMEM>>>(Sh, Vt, out, EMB, SEQ, 1.0f, Rs);
}

// round 7
// speedup vs baseline: 8.0565x; 1.0752x over previous
#include <cuda_runtime.h>
#include <cuda_fp16.h>
#include <cstdint>

#define SEQ 4096
#define EMB 1024

// ---------------- scratch (static, allocation-free) ----------------
__device__ __half g_Xh [(size_t)SEQ * EMB];
__device__ __half g_Wqt[(size_t)EMB * EMB];
__device__ __half g_Wkt[(size_t)EMB * EMB];
__device__ __half g_Wvt[(size_t)EMB * EMB];
__device__ __half g_Qh [(size_t)SEQ * EMB];
__device__ __half g_Kh [(size_t)SEQ * EMB];
__device__ __half g_Vh [(size_t)SEQ * EMB];
__device__ __half g_Vt [(size_t)EMB * SEQ];
__device__ __half g_Sh [(size_t)SEQ * SEQ];
__device__ float  g_part[(size_t)SEQ * 64];   // per (row, colCTA*2+wn) partials
__device__ float  g_rsum[SEQ];                // 1 / rowsum

// ---------------- helpers ----------------
__device__ __forceinline__ uint32_t smem_u32(const void* p) {
    return (uint32_t)__cvta_generic_to_shared(p);
}
__device__ __forceinline__ void cp16(uint32_t s, const void* g) {
    asm volatile("cp.async.cg.shared.global [%0], [%1], 16;" :: "r"(s), "l"(g));
}
__device__ __forceinline__ void cp_commit() {
    asm volatile("cp.async.commit_group;" ::: "memory");
}
template <int N>
__device__ __forceinline__ void cp_wait() {
    asm volatile("cp.async.wait_group %0;" :: "n"(N) : "memory");
}
__device__ __forceinline__ float ex2_mufu(float y) {
    float r;
    asm("ex2.approx.ftz.f32 %0, %1;" : "=f"(r) : "f"(y));
    return r;
}
// exact-split exp2 on the FMA pipe (y = n + f, f in [-.5,.5], degree-5 poly)
__device__ __forceinline__ float ex2_fma(float y) {
    const float MAGIC = 12582912.0f;          // 1.5 * 2^23
    float tm = __fadd_rn(y, MAGIC);
    float f  = __fadd_rn(y, -__fadd_rn(tm, -MAGIC));
    int   eb = (__float_as_int(tm) << 23) + 0x3F800000;
    float pl = 0.0013333558f;
    pl = fmaf(pl, f, 0.0096181291f);
    pl = fmaf(pl, f, 0.0555041087f);
    pl = fmaf(pl, f, 0.2402265069f);
    pl = fmaf(pl, f, 0.6931471806f);
    pl = fmaf(pl, f, 1.0f);
    return __int_as_float(eb) * pl;
}
// m16n8k16 fp16 MMA, fp32 accumulate
__device__ __forceinline__ void mma_f16(
    float& c0, float& c1, float& c2, float& c3,
    uint32_t a0, uint32_t a1, uint32_t a2, uint32_t a3,
    uint32_t b0, uint32_t b1)
{
    asm volatile(
        "mma.sync.aligned.m16n8k16.row.col.f32.f16.f16.f32 "
        "{%0,%1,%2,%3}, {%4,%5,%6,%7}, {%8,%9}, {%0,%1,%2,%3};"
        : "+f"(c0), "+f"(c1), "+f"(c2), "+f"(c3)
        : "r"(a0), "r"(a1), "r"(a2), "r"(a3), "r"(b0), "r"(b1));
}

// ---------------------------------------------------------------------------
// FP16 tensor-core NT GEMM: C[M,N] = f( A[M,K] @ B[N,K]^T )
// 128 threads (4 warps 2x2), warp tile 64x64, CTA tile 128x128, BK=64,
// 3-stage cp.async, one __syncthreads/iter, XOR-swizzled smem.
// MODE 0: fp16 out (projections)
// MODE 1: Sh = fp16(exp(alpha*acc)); per-(row,warp) partial sums -> part
// MODE 2: fp32 out scaled by alpha * rsum[row]   (rsum = reciprocal)
// ---------------------------------------------------------------------------
#define STG 3
#define OPW (128 * 32)                 // fp16x2 words per operand tile (16KB)
#define STW (2 * OPW)
#define GEMM_DYNSMEM (STG * STW * 4)   // 98304 bytes

template <int MODE>
__device__ __forceinline__ void gemm_body(
    const __half* __restrict__ A, const __half* __restrict__ B,
    void* __restrict__ Cv, int N, int K, float alpha,
    const float* __restrict__ rsum, float* __restrict__ part,
    int bm, int bn, int bx)
{
    extern __shared__ uint32_t sm[];

    const int tid  = threadIdx.x;
    const int warp = tid >> 5;
    const int lane = tid & 31;
    const int g    = lane >> 2;
    const int t    = lane & 3;
    const int wm   = warp & 1;      // 2 x 64 rows
    const int wn   = warp >> 1;     // 2 x 64 cols

    float acc[4][8][4];
    #pragma unroll
    for (int mi = 0; mi < 4; mi++)
        #pragma unroll
        for (int ni = 0; ni < 8; ni++)
            #pragma unroll
            for (int r = 0; r < 4; r++) acc[mi][ni][r] = 0.0f;

    const uint32_t smb = smem_u32(sm);
    const int lrow = tid >> 3;          // 0..15, 8 passes -> 128 rows
    const int lseg = tid & 7;

    auto load_stage = [&](int chunk) {
        const int s  = chunk % STG;
        const int k0 = chunk * 64;
        const uint32_t sa = smb + s * (STW * 4);
        const uint32_t sb = sa + OPW * 4;
        #pragma unroll
        for (int p = 0; p < 8; p++) {
            const int row  = lrow + p * 16;
            const int segS = lseg ^ (row & 7);
            const uint32_t so = (uint32_t)(row * 128 + segS * 16);
            cp16(sa + so, A + (size_t)(bm + row) * K + k0 + lseg * 8);
            cp16(sb + so, B + (size_t)(bn + row) * K + k0 + lseg * 8);
        }
        cp_commit();
    };

    const int NT = K >> 6;

    load_stage(0);
    load_stage(1);

    for (int i = 0; i < NT; i++) {
        const int s = i % STG;
        cp_wait<1>();
        __syncthreads();

        if (i + 2 < NT) load_stage(i + 2);
        else            cp_commit();

        const uint32_t* As  = sm + s * STW;
        const uint32_t* Bsm = As + OPW;
        const int swz = 4 * g;

        #pragma unroll
        for (int ksi = 0; ksi < 4; ksi++) {
            const int c0 = (ksi * 8 + t)     ^ swz;
            const int c2 = (ksi * 8 + t + 4) ^ swz;

            uint32_t af[4][4];
            #pragma unroll
            for (int mi = 0; mi < 4; mi++) {
                const uint32_t* base = As + (wm * 64 + mi * 16 + g) * 32;
                af[mi][0] = base[c0];
                af[mi][1] = base[8 * 32 + c0];
                af[mi][2] = base[c2];
                af[mi][3] = base[8 * 32 + c2];
            }
            uint32_t bf[8][2];
            #pragma unroll
            for (int ni = 0; ni < 8; ni++) {
                const uint32_t* base = Bsm + (wn * 64 + ni * 8 + g) * 32;
                bf[ni][0] = base[c0];
                bf[ni][1] = base[c2];
            }
            #pragma unroll
            for (int mi = 0; mi < 4; mi++)
                #pragma unroll
                for (int ni = 0; ni < 8; ni++)
                    mma_f16(acc[mi][ni][0], acc[mi][ni][1],
                            acc[mi][ni][2], acc[mi][ni][3],
                            af[mi][0], af[mi][1], af[mi][2], af[mi][3],
                            bf[ni][0], bf[ni][1]);
        }
    }

    // ---- epilogue ----
    if (MODE == 0) {
        __half* C = (__half*)Cv;
        #pragma unroll
        for (int mi = 0; mi < 4; mi++) {
            const int row = bm + wm * 64 + mi * 16 + g;
            #pragma unroll
            for (int ni = 0; ni < 8; ni++) {
                const int col = bn + wn * 64 + ni * 8 + 2 * t;
                *reinterpret_cast<__half2*>(&C[(size_t)row * N + col]) =
                    __floats2half2_rn(acc[mi][ni][0], acc[mi][ni][1]);
                *reinterpret_cast<__half2*>(&C[(size_t)(row + 8) * N + col]) =
                    __floats2half2_rn(acc[mi][ni][2], acc[mi][ni][3]);
            }
        }
    } else if (MODE == 1) {
        __half* C = (__half*)Cv;
        const float aL = alpha * 1.4426950408889634f;   // alpha * log2(e)
        #pragma unroll
        for (int mi = 0; mi < 4; mi++) {
            const int row = bm + wm * 64 + mi * 16 + g;
            float sr0 = 0.0f, sr1 = 0.0f;
            #pragma unroll
            for (int ni = 0; ni < 8; ni++) {
                const int col = bn + wn * 64 + ni * 8 + 2 * t;
                float v0, v1, v2, v3;
                if (ni & 1) {                 // FMA pipe
                    v0 = ex2_fma(acc[mi][ni][0] * aL);
                    v1 = ex2_fma(acc[mi][ni][1] * aL);
                    v2 = ex2_fma(acc[mi][ni][2] * aL);
                    v3 = ex2_fma(acc[mi][ni][3] * aL);
                } else {                      // MUFU pipe
                    v0 = ex2_mufu(acc[mi][ni][0] * aL);
                    v1 = ex2_mufu(acc[mi][ni][1] * aL);
                    v2 = ex2_mufu(acc[mi][ni][2] * aL);
                    v3 = ex2_mufu(acc[mi][ni][3] * aL);
                }
                *reinterpret_cast<__half2*>(&C[(size_t)row * N + col]) =
                    __floats2half2_rn(v0, v1);
                *reinterpret_cast<__half2*>(&C[(size_t)(row + 8) * N + col]) =
                    __floats2half2_rn(v2, v3);
                sr0 += v0 + v1;
                sr1 += v2 + v3;
            }
            // sum over the 4 t-lanes (same g)
            sr0 += __shfl_xor_sync(0xFFFFFFFF, sr0, 1);
            sr0 += __shfl_xor_sync(0xFFFFFFFF, sr0, 2);
            sr1 += __shfl_xor_sync(0xFFFFFFFF, sr1, 1);
            sr1 += __shfl_xor_sync(0xFFFFFFFF, sr1, 2);
            if (t == 0) {
                part[(size_t)row * 64 + bx * 2 + wn]       = sr0;
                part[(size_t)(row + 8) * 64 + bx * 2 + wn] = sr1;
            }
        }
    } else {
        float* C = (float*)Cv;
        #pragma unroll
        for (int mi = 0; mi < 4; mi++) {
            const int row = bm + wm * 64 + mi * 16 + g;
            const float s0 = alpha * __ldg(&rsum[row]);
            const float s1 = alpha * __ldg(&rsum[row + 8]);
            #pragma unroll
            for (int ni = 0; ni < 8; ni++) {
                const int col = bn + wn * 64 + ni * 8 + 2 * t;
                *reinterpret_cast<float2*>(&C[(size_t)row * N + col]) =
                    make_float2(acc[mi][ni][0] * s0, acc[mi][ni][1] * s0);
                *reinterpret_cast<float2*>(&C[(size_t)(row + 8) * N + col]) =
                    make_float2(acc[mi][ni][2] * s1, acc[mi][ni][3] * s1);
            }
        }
    }
}

// Fused Q/K/V projections (fp16 out), blockIdx.z selects weight/output.
__global__ void __launch_bounds__(128, 2) proj_k(
    const __half* __restrict__ Xh,
    const __half* __restrict__ B0, const __half* __restrict__ B1,
    const __half* __restrict__ B2,
    __half* __restrict__ C0, __half* __restrict__ C1, __half* __restrict__ C2)
{
    const int z = blockIdx.z;
    const __half* B = (z == 0) ? B0 : (z == 1) ? B1 : B2;
    __half*       C = (z == 0) ? C0 : (z == 1) ? C1 : C2;
    gemm_body<0>(Xh, B, C, EMB, EMB, 1.0f, nullptr, nullptr,
                 blockIdx.y * 128, blockIdx.x * 128, blockIdx.x);
}

// Score GEMM with fused exp + partial row sums.
__global__ void __launch_bounds__(128, 2) score_k(
    const __half* __restrict__ Q, const __half* __restrict__ Kh,
    __half* __restrict__ Sh, float* __restrict__ part)
{
    gemm_body<1>(Q, Kh, Sh, SEQ, EMB, 0.03125f, nullptr, part,
                 blockIdx.y * 128, blockIdx.x * 128, blockIdx.x);
}

// PV GEMM with 1/rowsum epilogue scaling.
__global__ void __launch_bounds__(128, 2) pv_k(
    const __half* __restrict__ Sh, const __half* __restrict__ Vt,
    float* __restrict__ out, const float* __restrict__ rsum)
{
    gemm_body<2>(Sh, Vt, out, EMB, SEQ, 1.0f, rsum, nullptr,
                 blockIdx.y * 128, blockIdx.x * 128, blockIdx.x);
}

// ---------------------------------------------------------------------------
// rowsum reduce: rsum[row] = 1 / sum(part[row][0..63])
// ---------------------------------------------------------------------------
__global__ void __launch_bounds__(256) rsum_k(const float* __restrict__ part,
                                              float* __restrict__ rsum)
{
    const int row = blockIdx.x * 256 + threadIdx.x;
    const float4* p = reinterpret_cast<const float4*>(part + (size_t)row * 64);
    float s = 0.0f;
    #pragma unroll
    for (int i = 0; i < 16; i++) {
        float4 v = p[i];
        s += (v.x + v.y) + (v.z + v.w);
    }
    rsum[row] = 1.0f / s;
}

// ---------------------------------------------------------------------------
// x fp32 -> fp16
// ---------------------------------------------------------------------------
__global__ void __launch_bounds__(256) cvtx_kernel(const float* __restrict__ in,
                                                   __half* __restrict__ out, int n4)
{
    int i = blockIdx.x * 256 + threadIdx.x;
    if (i < n4) {
        float4 v = reinterpret_cast<const float4*>(in)[i];
        __half2* o = reinterpret_cast<__half2*>(out) + i * 2;
        o[0] = __floats2half2_rn(v.x, v.y);
        o[1] = __floats2half2_rn(v.z, v.w);
    }
}

// ---------------------------------------------------------------------------
// Fused transpose of the 3 fp32 weight matrices -> fp16 (blockIdx.z selects).
// ---------------------------------------------------------------------------
__global__ void __launch_bounds__(256) wtrans_k(
    const float* __restrict__ Wq, const float* __restrict__ Wk,
    const float* __restrict__ Wv,
    __half* __restrict__ Tq, __half* __restrict__ Tk, __half* __restrict__ Tv)
{
    __shared__ float t[32][33];
    const int z = blockIdx.z;
    const float* in = (z == 0) ? Wq : (z == 1) ? Wk : Wv;
    __half*     out = (z == 0) ? Tq : (z == 1) ? Tk : Tv;

    const int bx = blockIdx.x * 32, by = blockIdx.y * 32;
    const int x = threadIdx.x, y = threadIdx.y;     // 32 x 8
    #pragma unroll
    for (int j = 0; j < 32; j += 8)
        t[y + j][x] = in[(size_t)(by + y + j) * EMB + bx + x];
    __syncthreads();
    #pragma unroll
    for (int j = 0; j < 32; j += 8)
        out[(size_t)(bx + y + j) * EMB + by + x] = __float2half(t[x][y + j]);
}

// ---------------------------------------------------------------------------
// fp16 transpose (V -> V^T)
// ---------------------------------------------------------------------------
__global__ void __launch_bounds__(256) htrans_k(const __half* __restrict__ in,
                                                __half* __restrict__ out,
                                                int R, int C)
{
    __shared__ __half t[32][34];
    const int bx = blockIdx.x * 32, by = blockIdx.y * 32;
    const int x = threadIdx.x, y = threadIdx.y;
    #pragma unroll
    for (int j = 0; j < 32; j += 8)
        t[y + j][x] = in[(size_t)(by + y + j) * C + bx + x];
    __syncthreads();
    #pragma unroll
    for (int j = 0; j < 32; j += 8)
        out[(size_t)(bx + y + j) * R + by + x] = t[x][y + j];
}

// ---------------------------------------------------------------------------
extern "C" void kernel_launch(void* const* d_in, const int* in_sizes, int n_in,
                              void* d_out, int out_size)
{
    const float* x  = (const float*)d_in[0];
    const float* Wq = (const float*)d_in[1];
    const float* Wk = (const float*)d_in[2];
    const float* Wv = (const float*)d_in[3];
    float* out = (float*)d_out;

    __half *Xh, *Wqt, *Wkt, *Wvt, *Qh, *Kh, *Vh, *Vt, *Sh;
    float *Part, *Rs;
    cudaGetSymbolAddress((void**)&Xh,  g_Xh);
    cudaGetSymbolAddress((void**)&Wqt, g_Wqt);
    cudaGetSymbolAddress((void**)&Wkt, g_Wkt);
    cudaGetSymbolAddress((void**)&Wvt, g_Wvt);
    cudaGetSymbolAddress((void**)&Qh,  g_Qh);
    cudaGetSymbolAddress((void**)&Kh,  g_Kh);
    cudaGetSymbolAddress((void**)&Vh,  g_Vh);
    cudaGetSymbolAddress((void**)&Vt,  g_Vt);
    cudaGetSymbolAddress((void**)&Sh,  g_Sh);
    cudaGetSymbolAddress((void**)&Part, g_part);
    cudaGetSymbolAddress((void**)&Rs,  g_rsum);

    cudaFuncSetAttribute(proj_k,
        cudaFuncAttributeMaxDynamicSharedMemorySize, GEMM_DYNSMEM);
    cudaFuncSetAttribute(score_k,
        cudaFuncAttributeMaxDynamicSharedMemorySize, GEMM_DYNSMEM);
    cudaFuncSetAttribute(pv_k,
        cudaFuncAttributeMaxDynamicSharedMemorySize, GEMM_DYNSMEM);

    const dim3 tblk(32, 8);
    const dim3 gW(EMB / 32, EMB / 32, 3);
    const dim3 gVt(EMB / 32, SEQ / 32);

    // Operand prep.
    cvtx_kernel<<<(SEQ * EMB / 4 + 255) / 256, 256>>>(x, Xh, SEQ * EMB / 4);
    wtrans_k<<<gW, tblk>>>(Wq, Wk, Wv, Wqt, Wkt, Wvt);

    const dim3 blk(128);
    const dim3 gProj(EMB / 128, SEQ / 128, 3);
    const dim3 gOne (EMB / 128, SEQ / 128);
    const dim3 gScore(SEQ / 128, SEQ / 128);

    // Projections (NT, fp16 out).
    proj_k<<<gProj, blk, GEMM_DYNSMEM>>>(Xh, Wqt, Wkt, Wvt, Qh, Kh, Vh);

    // V^T for the NT PV GEMM.
    htrans_k<<<gVt, tblk>>>(Vh, Vt, SEQ, EMB);

    // Scores + fused exp (fp16 out) + deterministic partial row sums.
    score_k<<<gScore, blk, GEMM_DYNSMEM>>>(Qh, Kh, Sh, Part);

    // Reduce partials -> reciprocal row sums.
    rsum_k<<<SEQ / 256, 256>>>(Part, Rs);

    // Output: out = diag(1/rowsum) * (expS @ Vt^T).
    pv_k<<<gOne, blk, GEMM_DYNSMEM>>>(Sh, Vt, out, Rs);
}